// round 8
// baseline (speedup 1.0000x reference)
#include <cuda_runtime.h>
#include <cstdint>

// YOLO loss, persistent-block + cp.async double-buffered pipeline.
// p, a: [N,7,7,30] f32 -> scalar. Only channels 10..29 are used by the
// reference (cls = 10..29, boxes = 20..29).
//
// ~5 blocks/SM, each grid-strides over 128-record tiles. Tile t+1 streams
// into the alternate smem buffer via cp.async (LDGSTS) while tile t is
// computed, so DRAM demand never idles during the compute phase.
// STRIDE=22 keeps every cp.async smem destination 8-byte aligned
// (STRIDE=21 caused the R6 misaligned-address fault); the resulting 2-way
// smem bank conflict on compute reads is not binding.
// Per-block partial -> last block (atomic ticket) reduces deterministically.

#define EPS_F 1e-6f
#define TILE 128          // records per tile == threads per block
#define STRIDE 22         // 20 channels + 2 pad; even -> 8B-aligned cp.async
#define GRID_BLOCKS 760   // 5 per SM (152 SMs)

__device__ float g_partials[8192];
__device__ unsigned int g_ticket;   // zero-init; reset by last block

__device__ __forceinline__ float signf(float x) {
    return (x > 0.f) ? 1.f : ((x < 0.f) ? -1.f : 0.f);
}

__device__ __forceinline__ float ssqrt(float x) {   // sign(x)*sqrt(x+EPS)
    float r;
    float xe = x + EPS_F;
    asm("sqrt.approx.f32 %0, %1;" : "=f"(r) : "f"(xe));
    return signf(x) * r;
}

// IoU as fraction n/d, d > 0; matches where(u==0,0,inter)/where(u==0,EPS,u).
__device__ __forceinline__ void iou_frac(
    float px, float py, float pw, float ph,
    float ax, float ay, float aw, float ah,
    float& n, float& d)
{
    float sx = fminf(px + pw * 0.5f, ax + aw * 0.5f)
             - fmaxf(px - pw * 0.5f, ax - aw * 0.5f);
    float sy = fminf(py + ph * 0.5f, ay + ah * 0.5f)
             - fmaxf(py - ph * 0.5f, ay - ah * 0.5f);
    sx = fmaxf(sx, 0.f);
    sy = fmaxf(sy, 0.f);
    float inter = sx * sy;
    float uni = fmaf(pw, ph, fmaf(aw, ah, -inter));
    bool z = (uni == 0.f);
    n = z ? 0.f : inter;
    d = z ? EPS_F : uni;
}

// Stage one tile's channels 10..29 (10 float2 per record, per tensor) into
// smem via cp.async. Fully unrolled; predicated for the (rare) partial tile.
__device__ __forceinline__ void stage_tile(
    const float2* __restrict__ p2, const float2* __restrict__ a2,
    uint32_t sp_addr, uint32_t sa_addr,
    long tileStart, int tid, int nrec)
{
    #pragma unroll
    for (int k = 0; k < 10; k++) {
        int i = tid + k * TILE;          // [0, 1280)
        int rec = i / 10;
        int j = i - rec * 10;
        long g = (tileStart + rec) * 15 + 5 + j;   // 120B record = 15 float2
        uint32_t d = (uint32_t)(rec * STRIDE + 2 * j) * 4u;  // rec*88+j*8: 8B-aligned
        if (rec < nrec) {
            asm volatile("cp.async.ca.shared.global [%0], [%1], 8;"
                         :: "r"(sp_addr + d), "l"(p2 + g));
            asm volatile("cp.async.ca.shared.global [%0], [%1], 8;"
                         :: "r"(sa_addr + d), "l"(a2 + g));
        }
    }
}

__device__ __forceinline__ float cell_loss(const float* cp, const float* ca)
{
    float px[2], py[2], pw[2], ph[2], pc[2];
    float qx[2], qy[2], qw[2], qh[2], qc[2];
    #pragma unroll
    for (int b = 0; b < 2; b++) {
        int o = 10 + 5 * b;              // channel 20+5b -> smem offset
        px[b] = cp[o]; py[b] = cp[o + 1]; pw[b] = cp[o + 2];
        ph[b] = cp[o + 3]; pc[b] = cp[o + 4];
        qx[b] = ca[o]; qy[b] = ca[o + 1]; qw[b] = ca[o + 2];
        qh[b] = ca[o + 3]; qc[b] = ca[o + 4];
    }

    float N[2], D[2];
    #pragma unroll
    for (int i = 0; i < 2; i++) {
        float n0, d0, n1, d1;
        iou_frac(px[i], py[i], pw[i], ph[i], qx[0], qy[0], qw[0], qh[0], n0, d0);
        iou_frac(px[i], py[i], pw[i], ph[i], qx[1], qy[1], qw[1], qh[1], n1, d1);
        bool take0 = (n0 * d1 >= n1 * d0);     // all d > 0
        N[i] = take0 ? n0 : n1;
        D[i] = take0 ? d0 : d1;
    }

    bool obj = qc[0] > 0.f;                    // a attr4 box0 (channel 24)
    bool resp0 = (N[0] * D[1] >= N[1] * D[0]); // argmax first-tie -> 0
    float ob[2];
    ob[0] = (obj && resp0)  ? 1.f : 0.f;
    ob[1] = (obj && !resp0) ? 1.f : 0.f;

    float coord = 0.f, cobj = 0.f, cnoobj = 0.f;
    #pragma unroll
    for (int b = 0; b < 2; b++) {
        float o = ob[b];
        float no = 1.f - o;
        float dx = o * qx[b] - o * px[b];
        float dy = o * qy[b] - o * py[b];
        coord += dx * dx + dy * dy;
        float dw = o * ssqrt(qw[b]) - o * ssqrt(pw[b]);
        float dh = o * ssqrt(qh[b]) - o * ssqrt(ph[b]);
        coord += dw * dw + dh * dh;
        float t1 = o * o - o * pc[b];
        cobj += t1 * t1;
        float t2 = no * o - no * pc[b];
        cnoobj += t2 * t2;
    }

    float cls = 0.f;
    if (obj) {
        #pragma unroll
        for (int k = 0; k < 20; k++) {
            float d = cp[k] - ca[k];
            cls += d * d;
        }
    }

    return 5.0f * coord + cobj + 0.5f * cnoobj + cls;
}

__global__ __launch_bounds__(TILE)
void yolo_loss_pipe(const float* __restrict__ p,
                    const float* __restrict__ a,
                    float* __restrict__ out,
                    int ncells, int ntiles)
{
    // double buffer: [buf][tensor(p=0,a=1)][TILE*STRIDE]
    __shared__ float sbuf[2][2][TILE * STRIDE];     // 45056 B
    __shared__ float warpsum[4];
    __shared__ bool s_last;

    const int tid = threadIdx.x;
    const float2* p2 = reinterpret_cast<const float2*>(p);
    const float2* a2 = reinterpret_cast<const float2*>(a);

    uint32_t sp_addr[2], sa_addr[2];
    #pragma unroll
    for (int b = 0; b < 2; b++) {
        sp_addr[b] = (uint32_t)__cvta_generic_to_shared(&sbuf[b][0][0]);
        sa_addr[b] = (uint32_t)__cvta_generic_to_shared(&sbuf[b][1][0]);
    }

    const int nblocks = gridDim.x;
    float acc = 0.f;
    int buf = 0;

    int tile0 = blockIdx.x;
    if (tile0 < ntiles) {
        // prologue: stage first tile
        {
            long ts = (long)tile0 * TILE;
            int nrec = min(TILE, ncells - (int)ts);
            stage_tile(p2, a2, sp_addr[0], sa_addr[0], ts, tid, nrec);
            asm volatile("cp.async.commit_group;" ::: "memory");
        }

        for (int tile = tile0; tile < ntiles; tile += nblocks) {
            int next = tile + nblocks;
            if (next < ntiles) {
                long ts = (long)next * TILE;
                int nrec = min(TILE, ncells - (int)ts);
                stage_tile(p2, a2, sp_addr[buf ^ 1], sa_addr[buf ^ 1], ts, tid, nrec);
                asm volatile("cp.async.commit_group;" ::: "memory");
                asm volatile("cp.async.wait_group 1;" ::: "memory");
            } else {
                asm volatile("cp.async.wait_group 0;" ::: "memory");
            }
            __syncthreads();   // tile's data visible to all threads

            int cell = tile * TILE + tid;
            if (cell < ncells)
                acc += cell_loss(&sbuf[buf][0][tid * STRIDE],
                                 &sbuf[buf][1][tid * STRIDE]);

            __syncthreads();   // all reads of this buffer done before reuse
            buf ^= 1;
        }
    }

    // ---- block reduction (4 warps) ----
    #pragma unroll
    for (int off = 16; off > 0; off >>= 1)
        acc += __shfl_down_sync(0xFFFFFFFFu, acc, off);
    if ((tid & 31) == 0) warpsum[tid >> 5] = acc;
    __syncthreads();

    if (tid == 0) {
        float v = warpsum[0] + warpsum[1] + warpsum[2] + warpsum[3];
        g_partials[blockIdx.x] = v;
        __threadfence();
        unsigned int t = atomicAdd(&g_ticket, 1u);
        s_last = (t == (unsigned int)(nblocks - 1));
    }
    __syncthreads();

    // ---- last block: deterministic final reduction + ticket reset ----
    if (s_last) {
        __threadfence();
        float s = 0.f;
        for (int i = tid; i < nblocks; i += TILE)
            s += g_partials[i];
        #pragma unroll
        for (int off = 16; off > 0; off >>= 1)
            s += __shfl_down_sync(0xFFFFFFFFu, s, off);
        if ((tid & 31) == 0) warpsum[tid >> 5] = s;
        __syncthreads();
        if (tid == 0) {
            out[0] = warpsum[0] + warpsum[1] + warpsum[2] + warpsum[3];
            g_ticket = 0;   // reset for next graph replay
        }
    }
}

extern "C" void kernel_launch(void* const* d_in, const int* in_sizes, int n_in,
                              void* d_out, int out_size)
{
    const float* p = (const float*)d_in[0];
    const float* a = (const float*)d_in[1];
    int ncells = in_sizes[0] / 30;                   // 16384*49 = 802816
    int ntiles = (ncells + TILE - 1) / TILE;         // 6272
    int blocks = GRID_BLOCKS < ntiles ? GRID_BLOCKS : ntiles;

    yolo_loss_pipe<<<blocks, TILE>>>(p, a, (float*)d_out, ncells, ntiles);
}

// round 11
// speedup vs baseline: 1.2244x; 1.2244x over previous
#include <cuda_runtime.h>
#include <cstdint>

// YOLO loss, persistent blocks + cp.async(16B) double-buffered pipeline.
// p, a: [N,7,7,30] f32 -> scalar.
//
// Each tile of 96 records is staged as one DENSE contiguous 16B-aligned
// stream (96*120 = 11520 B per tensor = 720 float4) via cp.async.cg.
// Earlier rounds requested only bytes [40,120) of each record with 8-B ops;
// that hole-punched misaligned stream capped DRAM at ~4 TB/s while still
// paying for full lines. Dense float4 staging costs the same bytes with a
// maximal-size aligned request stream.
//
// TILE=96 keeps the double buffer in 46 KB STATIC smem: no dynamic smem,
// no cudaFuncSetAttribute, no static guards in kernel_launch (harness rules).
// 4 blocks/SM, tile t+1 streams while tile t is computed. Last block
// (atomic ticket) reduces partials deterministically; ticket self-resets
// for graph replay.

#define EPS_F 1e-6f
#define TILE 96             // records per tile == threads per block
#define RSTRIDE 30          // floats per record in smem
#define F4_PER_TILE 720     // TILE*120/16
#define FLOATS_PER_BUF (TILE * RSTRIDE)        // 2880
#define BUF_FLOATS (2 * FLOATS_PER_BUF)        // p + a
#define GRID_BLOCKS 608     // 4 per SM (152 SMs)

__device__ float g_partials[8192];
__device__ unsigned int g_ticket;   // zero-init; reset by last block

__device__ __forceinline__ float signf(float x) {
    return (x > 0.f) ? 1.f : ((x < 0.f) ? -1.f : 0.f);
}

__device__ __forceinline__ float ssqrt(float x) {   // sign(x)*sqrt(x+EPS)
    float r;
    float xe = x + EPS_F;
    asm("sqrt.approx.f32 %0, %1;" : "=f"(r) : "f"(xe));
    return signf(x) * r;
}

// IoU as fraction n/d, d > 0; matches where(u==0,0,inter)/where(u==0,EPS,u).
__device__ __forceinline__ void iou_frac(
    float px, float py, float pw, float ph,
    float ax, float ay, float aw, float ah,
    float& n, float& d)
{
    float sx = fminf(px + pw * 0.5f, ax + aw * 0.5f)
             - fmaxf(px - pw * 0.5f, ax - aw * 0.5f);
    float sy = fminf(py + ph * 0.5f, ay + ah * 0.5f)
             - fmaxf(py - ph * 0.5f, ay - ah * 0.5f);
    sx = fmaxf(sx, 0.f);
    sy = fmaxf(sy, 0.f);
    float inter = sx * sy;
    float uni = fmaf(pw, ph, fmaf(aw, ah, -inter));
    bool z = (uni == 0.f);
    n = z ? 0.f : inter;
    d = z ? EPS_F : uni;
}

// Stage one tile: dense contiguous float4 copy of nrec*30 floats per tensor.
// Tile base byte offset = tileRec0*120, always 16B-aligned (120*96 ≡ 0 mod 16
// per full tile; tileRec0 is a multiple of 96 -> offset multiple of 11520).
__device__ __forceinline__ void stage_tile(
    const float* __restrict__ p, const float* __restrict__ a,
    uint32_t sp_addr, uint32_t sa_addr,
    long tileRec0, int tid, int nrec)
{
    if (nrec == TILE) {
        const float4* p4 = reinterpret_cast<const float4*>(p + tileRec0 * RSTRIDE);
        const float4* a4 = reinterpret_cast<const float4*>(a + tileRec0 * RSTRIDE);
        #pragma unroll
        for (int k = 0; k < 8; k++) {
            int i = tid + k * TILE;          // 720 = 7*96 + 48
            if (i < F4_PER_TILE) {
                asm volatile("cp.async.cg.shared.global [%0], [%1], 16;"
                             :: "r"(sp_addr + i * 16), "l"(p4 + i));
                asm volatile("cp.async.cg.shared.global [%0], [%1], 16;"
                             :: "r"(sa_addr + i * 16), "l"(a4 + i));
            }
        }
    } else {
        // generic tail tile: 4-byte copies (alignment-safe for any nrec)
        const float* pf = p + tileRec0 * RSTRIDE;
        const float* af = a + tileRec0 * RSTRIDE;
        int nfl = nrec * RSTRIDE;
        for (int i = tid; i < nfl; i += TILE) {
            asm volatile("cp.async.ca.shared.global [%0], [%1], 4;"
                         :: "r"(sp_addr + i * 4), "l"(pf + i));
            asm volatile("cp.async.ca.shared.global [%0], [%1], 4;"
                         :: "r"(sa_addr + i * 4), "l"(af + i));
        }
    }
}

__device__ __forceinline__ float cell_loss(const float* cp, const float* ca)
{
    // raw channels: boxes at 20+5b+i, cls at 10..29, a-conf box0 = ch 24
    float px[2], py[2], pw[2], ph[2], pc[2];
    float qx[2], qy[2], qw[2], qh[2], qc[2];
    #pragma unroll
    for (int b = 0; b < 2; b++) {
        int o = 20 + 5 * b;
        px[b] = cp[o]; py[b] = cp[o + 1]; pw[b] = cp[o + 2];
        ph[b] = cp[o + 3]; pc[b] = cp[o + 4];
        qx[b] = ca[o]; qy[b] = ca[o + 1]; qw[b] = ca[o + 2];
        qh[b] = ca[o + 3]; qc[b] = ca[o + 4];
    }

    float N[2], D[2];
    #pragma unroll
    for (int i = 0; i < 2; i++) {
        float n0, d0, n1, d1;
        iou_frac(px[i], py[i], pw[i], ph[i], qx[0], qy[0], qw[0], qh[0], n0, d0);
        iou_frac(px[i], py[i], pw[i], ph[i], qx[1], qy[1], qw[1], qh[1], n1, d1);
        bool take0 = (n0 * d1 >= n1 * d0);     // all d > 0
        N[i] = take0 ? n0 : n1;
        D[i] = take0 ? d0 : d1;
    }

    bool obj = qc[0] > 0.f;
    bool resp0 = (N[0] * D[1] >= N[1] * D[0]); // argmax first-tie -> 0
    float ob[2];
    ob[0] = (obj && resp0)  ? 1.f : 0.f;
    ob[1] = (obj && !resp0) ? 1.f : 0.f;

    float coord = 0.f, cobj = 0.f, cnoobj = 0.f;
    #pragma unroll
    for (int b = 0; b < 2; b++) {
        float o = ob[b];
        float no = 1.f - o;
        float dx = o * qx[b] - o * px[b];
        float dy = o * qy[b] - o * py[b];
        coord += dx * dx + dy * dy;
        float dw = o * ssqrt(qw[b]) - o * ssqrt(pw[b]);
        float dh = o * ssqrt(qh[b]) - o * ssqrt(ph[b]);
        coord += dw * dw + dh * dh;
        float t1 = o * o - o * pc[b];
        cobj += t1 * t1;
        float t2 = no * o - no * pc[b];
        cnoobj += t2 * t2;
    }

    float cls = 0.f;
    if (obj) {
        #pragma unroll
        for (int k = 10; k < 30; k++) {
            float d = cp[k] - ca[k];
            cls += d * d;
        }
    }

    return 5.0f * coord + cobj + 0.5f * cnoobj + cls;
}

__global__ __launch_bounds__(TILE)
void yolo_loss_pipe(const float* __restrict__ p,
                    const float* __restrict__ a,
                    float* __restrict__ out,
                    int ncells, int ntiles)
{
    // double buffer: [buf] { p-tile (2880 f), a-tile (2880 f) } = 46080 B
    __shared__ float sbuf[2][BUF_FLOATS];
    __shared__ float warpsum[3];
    __shared__ bool s_last;

    const int tid = threadIdx.x;

    uint32_t sp_addr[2], sa_addr[2];
    #pragma unroll
    for (int b = 0; b < 2; b++) {
        sp_addr[b] = (uint32_t)__cvta_generic_to_shared(&sbuf[b][0]);
        sa_addr[b] = sp_addr[b] + FLOATS_PER_BUF * 4;
    }

    const int nblocks = gridDim.x;
    float acc = 0.f;
    int buf = 0;

    int tile0 = blockIdx.x;
    if (tile0 < ntiles) {
        {   // prologue
            long r0 = (long)tile0 * TILE;
            int nrec = min(TILE, ncells - (int)r0);
            stage_tile(p, a, sp_addr[0], sa_addr[0], r0, tid, nrec);
            asm volatile("cp.async.commit_group;" ::: "memory");
        }

        for (int tile = tile0; tile < ntiles; tile += nblocks) {
            int next = tile + nblocks;
            if (next < ntiles) {
                long r0 = (long)next * TILE;
                int nrec = min(TILE, ncells - (int)r0);
                stage_tile(p, a, sp_addr[buf ^ 1], sa_addr[buf ^ 1], r0, tid, nrec);
                asm volatile("cp.async.commit_group;" ::: "memory");
                asm volatile("cp.async.wait_group 1;" ::: "memory");
            } else {
                asm volatile("cp.async.wait_group 0;" ::: "memory");
            }
            __syncthreads();   // tile data visible to all threads

            int cell = tile * TILE + tid;
            if (cell < ncells)
                acc += cell_loss(&sbuf[buf][tid * RSTRIDE],
                                 &sbuf[buf][FLOATS_PER_BUF + tid * RSTRIDE]);

            __syncthreads();   // reads done before buffer reuse
            buf ^= 1;
        }
    }

    // ---- block reduction (3 warps) ----
    #pragma unroll
    for (int off = 16; off > 0; off >>= 1)
        acc += __shfl_down_sync(0xFFFFFFFFu, acc, off);
    if ((tid & 31) == 0) warpsum[tid >> 5] = acc;
    __syncthreads();

    if (tid == 0) {
        float v = warpsum[0] + warpsum[1] + warpsum[2];
        g_partials[blockIdx.x] = v;
        __threadfence();
        unsigned int t = atomicAdd(&g_ticket, 1u);
        s_last = (t == (unsigned int)(nblocks - 1));
    }
    __syncthreads();

    // ---- last block: deterministic final reduction + ticket reset ----
    if (s_last) {
        __threadfence();
        float s = 0.f;
        for (int i = tid; i < nblocks; i += TILE)
            s += g_partials[i];
        #pragma unroll
        for (int off = 16; off > 0; off >>= 1)
            s += __shfl_down_sync(0xFFFFFFFFu, s, off);
        if ((tid & 31) == 0) warpsum[tid >> 5] = s;
        __syncthreads();
        if (tid == 0) {
            out[0] = warpsum[0] + warpsum[1] + warpsum[2];
            g_ticket = 0;   // reset for next graph replay
        }
    }
}

extern "C" void kernel_launch(void* const* d_in, const int* in_sizes, int n_in,
                              void* d_out, int out_size)
{
    const float* p = (const float*)d_in[0];
    const float* a = (const float*)d_in[1];
    int ncells = in_sizes[0] / 30;                   // 802816
    int ntiles = (ncells + TILE - 1) / TILE;         // 8363
    int blocks = GRID_BLOCKS < ntiles ? GRID_BLOCKS : ntiles;

    yolo_loss_pipe<<<blocks, TILE>>>(p, a, (float*)d_out, ncells, ntiles);
}